// round 1
// baseline (speedup 1.0000x reference)
#include <cuda_runtime.h>
#include <cstdint>

#define N_NODES 50000
#define D 128
#define NB4 (N_NODES * D / 4)

// Scratch: aggregation buffer (device global — no allocation allowed).
__device__ float g_agg[(size_t)N_NODES * D];

// ---------------------------------------------------------------------------
// Kernel 1: zero the aggregation buffer (float4 grid-stride).
// ---------------------------------------------------------------------------
__global__ void zero_agg_kernel() {
    float4* p = reinterpret_cast<float4*>(g_agg);
    const float4 z = make_float4(0.f, 0.f, 0.f, 0.f);
    for (int i = blockIdx.x * blockDim.x + threadIdx.x; i < NB4;
         i += gridDim.x * blockDim.x) {
        p[i] = z;
    }
}

// ---------------------------------------------------------------------------
// Kernel 2: edge scatter. One warp per edge; lane l handles features
// [4l, 4l+4). Vector reduction (red.global.add.v4.f32) to cut LTS atomic
// op count 4x vs scalar atomicAdd.
// ---------------------------------------------------------------------------
__global__ void scatter_edges_kernel(const float* __restrict__ feat,
                                     const int* __restrict__ src,
                                     const int* __restrict__ dst,
                                     const float* __restrict__ ew,
                                     int E) {
    int gid  = blockIdx.x * blockDim.x + threadIdx.x;
    int e    = gid >> 5;
    int lane = gid & 31;
    if (e >= E) return;

    int   s  = __ldg(src + e);
    int   d  = __ldg(dst + e);
    float wt = __ldg(ew + e);

    const float4* frow = reinterpret_cast<const float4*>(feat + (size_t)s * D);
    float4 v = __ldg(frow + lane);
    v.x *= wt; v.y *= wt; v.z *= wt; v.w *= wt;

    float* outp = g_agg + (size_t)d * D + lane * 4;
    asm volatile("red.global.add.v4.f32 [%0], {%1, %2, %3, %4};"
                 :: "l"(outp), "f"(v.x), "f"(v.y), "f"(v.z), "f"(v.w)
                 : "memory");
}

// ---------------------------------------------------------------------------
// Kernel 3: blended = 0.5*agg + 0.5*feature, then out = blended @ W.
// Block = 256 threads = 8 warps; block handles 16 rows (2 rows per warp).
// A-rows staged in smem (warp-broadcast reads, conflict-free).
// Weight rows read as float4 (coalesced; 64KB total, L1/L2 hot).
// Each lane owns 4 output columns for 2 rows -> weight load amortized
// over 8 FMAs.
// ---------------------------------------------------------------------------
__global__ void __launch_bounds__(256)
gemm_blend_kernel(const float* __restrict__ feat,
                  const float* __restrict__ W,
                  float* __restrict__ out) {
    __shared__ float sA[16][D];

    const int block_row = blockIdx.x * 16;
    const int t = threadIdx.x;

    // Cooperative load + blend: 16 rows * 32 float4 = 512 float4, 2 per thread.
    for (int i = t; i < 16 * (D / 4); i += 256) {
        int r  = i >> 5;          // row within tile
        int c4 = i & 31;          // float4 index within row
        size_t g = (size_t)(block_row + r) * D + c4 * 4;
        float4 a = *reinterpret_cast<const float4*>(g_agg + g);
        float4 f = __ldg(reinterpret_cast<const float4*>(feat + g));
        float4 b;
        b.x = 0.5f * (a.x + f.x);
        b.y = 0.5f * (a.y + f.y);
        b.z = 0.5f * (a.z + f.z);
        b.w = 0.5f * (a.w + f.w);
        *reinterpret_cast<float4*>(&sA[r][c4 * 4]) = b;
    }
    __syncthreads();

    const int warp = t >> 5;
    const int lane = t & 31;
    const int r0 = warp * 2;
    const int r1 = r0 + 1;

    float4 acc0 = make_float4(0.f, 0.f, 0.f, 0.f);
    float4 acc1 = make_float4(0.f, 0.f, 0.f, 0.f);

    const float4* W4 = reinterpret_cast<const float4*>(W);

    #pragma unroll 8
    for (int k = 0; k < D; k++) {
        float4 wv = __ldg(W4 + k * (D / 4) + lane);
        float a0 = sA[r0][k];
        float a1 = sA[r1][k];
        acc0.x += a0 * wv.x; acc0.y += a0 * wv.y;
        acc0.z += a0 * wv.z; acc0.w += a0 * wv.w;
        acc1.x += a1 * wv.x; acc1.y += a1 * wv.y;
        acc1.z += a1 * wv.z; acc1.w += a1 * wv.w;
    }

    reinterpret_cast<float4*>(out + (size_t)(block_row + r0) * D)[lane] = acc0;
    reinterpret_cast<float4*>(out + (size_t)(block_row + r1) * D)[lane] = acc1;
}

// ---------------------------------------------------------------------------
// Launch. Inputs (metadata order): feature [N*D] f32, edge_src [E] i32,
// edge_dst [E] i32, edge_w [E] f32, weight [D*D] f32. Output: [N*D] f32.
// ---------------------------------------------------------------------------
extern "C" void kernel_launch(void* const* d_in, const int* in_sizes, int n_in,
                              void* d_out, int out_size) {
    const float* feat = (const float*)d_in[0];
    const int*   src  = (const int*)d_in[1];
    const int*   dst  = (const int*)d_in[2];
    const float* ew   = (const float*)d_in[3];
    const float* W    = (const float*)d_in[4];
    float* out = (float*)d_out;

    const int E = in_sizes[1];

    // 1) zero agg
    zero_agg_kernel<<<592, 256>>>();   // 4 blocks/SM * 148

    // 2) scatter edges: one warp per edge
    {
        long long total_threads = (long long)E * 32;
        int block = 256;
        int grid = (int)((total_threads + block - 1) / block);
        scatter_edges_kernel<<<grid, block>>>(feat, src, dst, ew, E);
    }

    // 3) blend + GEMM: 16 rows per block
    {
        int grid = (N_NODES + 15) / 16;  // 3125
        gemm_blend_kernel<<<grid, 256>>>(feat, W, out);
    }
}

// round 2
// speedup vs baseline: 1.2101x; 1.2101x over previous
#include <cuda_runtime.h>
#include <cstdint>

#define N_NODES 50000
#define D       128
#define E_MAX   800000
#define SCAN_BS 1024
#define SCAN_NBLK ((N_NODES + SCAN_BS - 1) / SCAN_BS)   // 49

// ---- scratch (static device globals; no allocation allowed) ----
__device__ float g_P[(size_t)N_NODES * D];      // P = feat @ W
__device__ int   g_counts[N_NODES];             // degree histogram (by dst)
__device__ int   g_incl[SCAN_NBLK * SCAN_BS];   // per-block inclusive scan
__device__ int   g_blocksum[SCAN_NBLK];
__device__ int   g_blockoff[SCAN_NBLK];
__device__ int   g_rowstart[N_NODES];           // exclusive prefix (CSR row ptr)
__device__ int   g_cursor[N_NODES];             // fill cursors
__device__ int   g_csr_src[E_MAX];
__device__ float g_csr_w[E_MAX];

// ---------------------------------------------------------------------------
// CSR build
// ---------------------------------------------------------------------------
__global__ void zero_counts_kernel() {
    int i = blockIdx.x * blockDim.x + threadIdx.x;
    if (i < N_NODES) g_counts[i] = 0;
}

__global__ void hist_kernel(const int* __restrict__ dst, int E) {
    int i = blockIdx.x * blockDim.x + threadIdx.x;
    if (i < E) atomicAdd(&g_counts[__ldg(dst + i)], 1);
}

__global__ void scan1_kernel() {
    __shared__ int s[SCAN_BS];
    int t = threadIdx.x;
    int idx = blockIdx.x * SCAN_BS + t;
    int v = (idx < N_NODES) ? g_counts[idx] : 0;
    s[t] = v;
    __syncthreads();
    #pragma unroll
    for (int off = 1; off < SCAN_BS; off <<= 1) {
        int x = (t >= off) ? s[t - off] : 0;
        __syncthreads();
        s[t] += x;
        __syncthreads();
    }
    g_incl[idx] = s[t];
    if (t == SCAN_BS - 1) g_blocksum[blockIdx.x] = s[t];
}

__global__ void scan2_kernel() {
    // tiny serial exclusive scan of block sums
    if (threadIdx.x == 0) {
        int run = 0;
        for (int b = 0; b < SCAN_NBLK; b++) {
            g_blockoff[b] = run;
            run += g_blocksum[b];
        }
    }
}

__global__ void scan3_kernel() {
    int idx = blockIdx.x * SCAN_BS + threadIdx.x;
    if (idx < N_NODES) {
        // exclusive = inclusive - self + block offset
        int rs = g_incl[idx] - g_counts[idx] + g_blockoff[blockIdx.x];
        g_rowstart[idx] = rs;
        g_cursor[idx]   = rs;
    }
}

__global__ void fill_kernel(const int* __restrict__ src,
                            const int* __restrict__ dst,
                            const float* __restrict__ ew, int E) {
    int i = blockIdx.x * blockDim.x + threadIdx.x;
    if (i < E) {
        int d = __ldg(dst + i);
        int p = atomicAdd(&g_cursor[d], 1);
        g_csr_src[p] = __ldg(src + i);
        g_csr_w[p]   = __ldg(ew + i);
    }
}

// ---------------------------------------------------------------------------
// GEMM: P = feat @ W.  16 rows per 256-thread block; 2 rows per warp;
// lane owns 4 output columns per row.
// ---------------------------------------------------------------------------
__global__ void __launch_bounds__(256)
gemm_kernel(const float* __restrict__ feat, const float* __restrict__ W) {
    __shared__ float sA[16][D];

    const int block_row = blockIdx.x * 16;
    const int t = threadIdx.x;

    for (int i = t; i < 16 * (D / 4); i += 256) {
        int r  = i >> 5;
        int c4 = i & 31;
        float4 f = __ldg(reinterpret_cast<const float4*>(
            feat + (size_t)(block_row + r) * D + c4 * 4));
        *reinterpret_cast<float4*>(&sA[r][c4 * 4]) = f;
    }
    __syncthreads();

    const int warp = t >> 5;
    const int lane = t & 31;
    const int r0 = warp * 2;
    const int r1 = r0 + 1;

    float4 acc0 = make_float4(0.f, 0.f, 0.f, 0.f);
    float4 acc1 = make_float4(0.f, 0.f, 0.f, 0.f);

    const float4* W4 = reinterpret_cast<const float4*>(W);

    #pragma unroll 8
    for (int k = 0; k < D; k++) {
        float4 wv = __ldg(W4 + k * (D / 4) + lane);
        float a0 = sA[r0][k];
        float a1 = sA[r1][k];
        acc0.x += a0 * wv.x; acc0.y += a0 * wv.y;
        acc0.z += a0 * wv.z; acc0.w += a0 * wv.w;
        acc1.x += a1 * wv.x; acc1.y += a1 * wv.y;
        acc1.z += a1 * wv.z; acc1.w += a1 * wv.w;
    }

    reinterpret_cast<float4*>(g_P + (size_t)(block_row + r0) * D)[lane] = acc0;
    reinterpret_cast<float4*>(g_P + (size_t)(block_row + r1) * D)[lane] = acc1;
}

// ---------------------------------------------------------------------------
// Gather: out[n] = 0.5*(P[n] + sum_e w_e * P[src_e]).  One warp per node,
// lane handles 4 features. 4-edge unroll for MLP.
// ---------------------------------------------------------------------------
__global__ void __launch_bounds__(256)
gather_kernel(float* __restrict__ out) {
    int gid  = blockIdx.x * blockDim.x + threadIdx.x;
    int node = gid >> 5;
    int lane = gid & 31;
    if (node >= N_NODES) return;

    const float4* P4 = reinterpret_cast<const float4*>(g_P);
    const int start = g_rowstart[node];
    const int cnt   = g_counts[node];

    float4 acc = P4[(size_t)node * 32 + lane];

    int i = 0;
    for (; i + 4 <= cnt; i += 4) {
        int   s0 = g_csr_src[start + i + 0];
        int   s1 = g_csr_src[start + i + 1];
        int   s2 = g_csr_src[start + i + 2];
        int   s3 = g_csr_src[start + i + 3];
        float w0 = g_csr_w[start + i + 0];
        float w1 = g_csr_w[start + i + 1];
        float w2 = g_csr_w[start + i + 2];
        float w3 = g_csr_w[start + i + 3];
        float4 v0 = P4[(size_t)s0 * 32 + lane];
        float4 v1 = P4[(size_t)s1 * 32 + lane];
        float4 v2 = P4[(size_t)s2 * 32 + lane];
        float4 v3 = P4[(size_t)s3 * 32 + lane];
        acc.x += w0 * v0.x + w1 * v1.x + w2 * v2.x + w3 * v3.x;
        acc.y += w0 * v0.y + w1 * v1.y + w2 * v2.y + w3 * v3.y;
        acc.z += w0 * v0.z + w1 * v1.z + w2 * v2.z + w3 * v3.z;
        acc.w += w0 * v0.w + w1 * v1.w + w2 * v2.w + w3 * v3.w;
    }
    for (; i < cnt; i++) {
        int   s = g_csr_src[start + i];
        float w = g_csr_w[start + i];
        float4 v = P4[(size_t)s * 32 + lane];
        acc.x += w * v.x; acc.y += w * v.y;
        acc.z += w * v.z; acc.w += w * v.w;
    }

    acc.x *= 0.5f; acc.y *= 0.5f; acc.z *= 0.5f; acc.w *= 0.5f;
    reinterpret_cast<float4*>(out)[(size_t)node * 32 + lane] = acc;
}

// ---------------------------------------------------------------------------
// Launch. Inputs: feature [N*D] f32, edge_src [E] i32, edge_dst [E] i32,
// edge_w [E] f32, weight [D*D] f32. Output: [N*D] f32.
// ---------------------------------------------------------------------------
extern "C" void kernel_launch(void* const* d_in, const int* in_sizes, int n_in,
                              void* d_out, int out_size) {
    const float* feat = (const float*)d_in[0];
    const int*   src  = (const int*)d_in[1];
    const int*   dst  = (const int*)d_in[2];
    const float* ew   = (const float*)d_in[3];
    const float* W    = (const float*)d_in[4];
    float* out = (float*)d_out;

    const int E = in_sizes[1];
    const int eg = (E + 255) / 256;

    // CSR build
    zero_counts_kernel<<<(N_NODES + 255) / 256, 256>>>();
    hist_kernel<<<eg, 256>>>(dst, E);
    scan1_kernel<<<SCAN_NBLK, SCAN_BS>>>();
    scan2_kernel<<<1, 32>>>();
    scan3_kernel<<<SCAN_NBLK, SCAN_BS>>>();
    fill_kernel<<<eg, 256>>>(src, dst, ew, E);

    // P = feat @ W
    gemm_kernel<<<(N_NODES + 15) / 16, 256>>>(feat, W);

    // out = 0.5*(P + sum w*P[src])
    gather_kernel<<<(N_NODES * 32 + 255) / 256, 256>>>(out);
}

// round 3
// speedup vs baseline: 1.2260x; 1.0132x over previous
#include <cuda_runtime.h>
#include <cstdint>

#define N_NODES 50000
#define D       128
#define E_MAX   800000
#define SCAN_BS 1024
#define SCAN_NBLK ((N_NODES + SCAN_BS - 1) / SCAN_BS)   // 49

// ---- scratch (static device globals; no allocation allowed) ----
__device__ float g_P[(size_t)N_NODES * D];      // P = feat @ W
__device__ int   g_counts[N_NODES];             // degree histogram (by dst)
__device__ int   g_incl[SCAN_NBLK * SCAN_BS];   // per-block inclusive scan
__device__ int   g_blocksum[SCAN_NBLK];
__device__ int   g_blockoff[SCAN_NBLK];
__device__ int   g_rowstart[N_NODES];           // exclusive prefix (CSR row ptr)
__device__ int   g_cursor[N_NODES];             // fill cursors
__device__ int   g_csr_src[E_MAX];
__device__ float g_csr_w[E_MAX];

// ---- f32x2 packed-FMA helpers (sm_103a) ----
__device__ __forceinline__ void fma2(unsigned long long& d,
                                     unsigned long long a,
                                     unsigned long long b) {
    asm("fma.rn.f32x2 %0, %1, %2, %0;" : "+l"(d) : "l"(a), "l"(b));
}
__device__ __forceinline__ unsigned long long packdup(float x) {
    unsigned long long r;
    asm("mov.b64 %0, {%1, %1};" : "=l"(r) : "f"(x));
    return r;
}
__device__ __forceinline__ float2 unpack2(unsigned long long v) {
    float2 r;
    asm("mov.b64 {%0, %1}, %2;" : "=f"(r.x), "=f"(r.y) : "l"(v));
    return r;
}

// ---------------------------------------------------------------------------
// CSR build
// ---------------------------------------------------------------------------
__global__ void zero_counts_kernel() {
    int i = blockIdx.x * blockDim.x + threadIdx.x;
    if (i < N_NODES) g_counts[i] = 0;
}

__global__ void hist_kernel(const int* __restrict__ dst, int E) {
    int i = blockIdx.x * blockDim.x + threadIdx.x;
    if (i < E) atomicAdd(&g_counts[__ldg(dst + i)], 1);
}

__global__ void scan1_kernel() {
    __shared__ int s[SCAN_BS];
    int t = threadIdx.x;
    int idx = blockIdx.x * SCAN_BS + t;
    int v = (idx < N_NODES) ? g_counts[idx] : 0;
    s[t] = v;
    __syncthreads();
    #pragma unroll
    for (int off = 1; off < SCAN_BS; off <<= 1) {
        int x = (t >= off) ? s[t - off] : 0;
        __syncthreads();
        s[t] += x;
        __syncthreads();
    }
    g_incl[idx] = s[t];
    if (t == SCAN_BS - 1) g_blocksum[blockIdx.x] = s[t];
}

// warp-shuffle exclusive scan of the 49 block sums (2 elements per lane)
__global__ void scan2_kernel() {
    int l = threadIdx.x;            // 32 threads
    int i0 = 2 * l, i1 = 2 * l + 1;
    int v0 = (i0 < SCAN_NBLK) ? g_blocksum[i0] : 0;
    int v1 = (i1 < SCAN_NBLK) ? g_blocksum[i1] : 0;
    int s = v0 + v1;
    int x = s;
    #pragma unroll
    for (int off = 1; off < 32; off <<= 1) {
        int y = __shfl_up_sync(0xFFFFFFFFu, x, off);
        if (l >= off) x += y;
    }
    int excl = x - s;               // exclusive prefix of this lane's pair
    if (i0 < SCAN_NBLK) g_blockoff[i0] = excl;
    if (i1 < SCAN_NBLK) g_blockoff[i1] = excl + v0;
}

__global__ void scan3_kernel() {
    int idx = blockIdx.x * SCAN_BS + threadIdx.x;
    if (idx < N_NODES) {
        int rs = g_incl[idx] - g_counts[idx] + g_blockoff[blockIdx.x];
        g_rowstart[idx] = rs;
        g_cursor[idx]   = rs;
    }
}

__global__ void fill_kernel(const int* __restrict__ src,
                            const int* __restrict__ dst,
                            const float* __restrict__ ew, int E) {
    int i = blockIdx.x * blockDim.x + threadIdx.x;
    if (i < E) {
        int d = __ldg(dst + i);
        int p = atomicAdd(&g_cursor[d], 1);
        g_csr_src[p] = __ldg(src + i);
        g_csr_w[p]   = __ldg(ew + i);
    }
}

// ---------------------------------------------------------------------------
// GEMM: P = feat @ W.  16 rows / 256-thread block, 2 rows per warp,
// lane owns 4 output columns. f32x2 packed FMA: 4 packed FMAs per k per
// thread instead of 8 scalar FFMAs.
// ---------------------------------------------------------------------------
__global__ void __launch_bounds__(256)
gemm_kernel(const float* __restrict__ feat, const float* __restrict__ W) {
    __shared__ float sA[16][D];

    const int block_row = blockIdx.x * 16;
    const int t = threadIdx.x;

    for (int i = t; i < 16 * (D / 4); i += 256) {
        int r  = i >> 5;
        int c4 = i & 31;
        float4 f = __ldg(reinterpret_cast<const float4*>(
            feat + (size_t)(block_row + r) * D + c4 * 4));
        *reinterpret_cast<float4*>(&sA[r][c4 * 4]) = f;
    }
    __syncthreads();

    const int warp = t >> 5;
    const int lane = t & 31;
    const int r0 = warp * 2;
    const int r1 = r0 + 1;

    unsigned long long acc0a = 0, acc0b = 0, acc1a = 0, acc1b = 0;

    // W row k as packed pairs: 128 floats = 32 ulonglong2 per row.
    const ulonglong2* W8 = reinterpret_cast<const ulonglong2*>(W);

    #pragma unroll 8
    for (int k = 0; k < D; k++) {
        ulonglong2 w = __ldg(W8 + k * (D / 4) + lane);  // cols [4*lane, 4*lane+4)
        unsigned long long a0 = packdup(sA[r0][k]);
        unsigned long long a1 = packdup(sA[r1][k]);
        fma2(acc0a, w.x, a0);
        fma2(acc0b, w.y, a0);
        fma2(acc1a, w.x, a1);
        fma2(acc1b, w.y, a1);
    }

    float2 p0 = unpack2(acc0a), p1 = unpack2(acc0b);
    float2 p2 = unpack2(acc1a), p3 = unpack2(acc1b);
    reinterpret_cast<float4*>(g_P + (size_t)(block_row + r0) * D)[lane] =
        make_float4(p0.x, p0.y, p1.x, p1.y);
    reinterpret_cast<float4*>(g_P + (size_t)(block_row + r1) * D)[lane] =
        make_float4(p2.x, p2.y, p3.x, p3.y);
}

// ---------------------------------------------------------------------------
// Gather: out[n] = 0.5*(P[n] + sum_e w_e * P[src_e]).  One warp per node,
// lane handles 4 features. 4-edge unroll for MLP.
// ---------------------------------------------------------------------------
__global__ void __launch_bounds__(256)
gather_kernel(float* __restrict__ out) {
    int gid  = blockIdx.x * blockDim.x + threadIdx.x;
    int node = gid >> 5;
    int lane = gid & 31;
    if (node >= N_NODES) return;

    const float4* P4 = reinterpret_cast<const float4*>(g_P);
    const int start = g_rowstart[node];
    const int cnt   = g_counts[node];

    float4 acc = P4[(size_t)node * 32 + lane];

    int i = 0;
    for (; i + 4 <= cnt; i += 4) {
        int   s0 = g_csr_src[start + i + 0];
        int   s1 = g_csr_src[start + i + 1];
        int   s2 = g_csr_src[start + i + 2];
        int   s3 = g_csr_src[start + i + 3];
        float w0 = g_csr_w[start + i + 0];
        float w1 = g_csr_w[start + i + 1];
        float w2 = g_csr_w[start + i + 2];
        float w3 = g_csr_w[start + i + 3];
        float4 v0 = P4[(size_t)s0 * 32 + lane];
        float4 v1 = P4[(size_t)s1 * 32 + lane];
        float4 v2 = P4[(size_t)s2 * 32 + lane];
        float4 v3 = P4[(size_t)s3 * 32 + lane];
        acc.x += w0 * v0.x + w1 * v1.x + w2 * v2.x + w3 * v3.x;
        acc.y += w0 * v0.y + w1 * v1.y + w2 * v2.y + w3 * v3.y;
        acc.z += w0 * v0.z + w1 * v1.z + w2 * v2.z + w3 * v3.z;
        acc.w += w0 * v0.w + w1 * v1.w + w2 * v2.w + w3 * v3.w;
    }
    for (; i < cnt; i++) {
        int   s = g_csr_src[start + i];
        float w = g_csr_w[start + i];
        float4 v = P4[(size_t)s * 32 + lane];
        acc.x += w * v.x; acc.y += w * v.y;
        acc.z += w * v.z; acc.w += w * v.w;
    }

    acc.x *= 0.5f; acc.y *= 0.5f; acc.z *= 0.5f; acc.w *= 0.5f;
    reinterpret_cast<float4*>(out)[(size_t)node * 32 + lane] = acc;
}

// ---------------------------------------------------------------------------
// Launch. Inputs: feature [N*D] f32, edge_src [E] i32, edge_dst [E] i32,
// edge_w [E] f32, weight [D*D] f32. Output: [N*D] f32.
// ---------------------------------------------------------------------------
extern "C" void kernel_launch(void* const* d_in, const int* in_sizes, int n_in,
                              void* d_out, int out_size) {
    const float* feat = (const float*)d_in[0];
    const int*   src  = (const int*)d_in[1];
    const int*   dst  = (const int*)d_in[2];
    const float* ew   = (const float*)d_in[3];
    const float* W    = (const float*)d_in[4];
    float* out = (float*)d_out;

    const int E = in_sizes[1];
    const int eg = (E + 255) / 256;

    // CSR build
    zero_counts_kernel<<<(N_NODES + 255) / 256, 256>>>();
    hist_kernel<<<eg, 256>>>(dst, E);
    scan1_kernel<<<SCAN_NBLK, SCAN_BS>>>();
    scan2_kernel<<<1, 32>>>();
    scan3_kernel<<<SCAN_NBLK, SCAN_BS>>>();
    fill_kernel<<<eg, 256>>>(src, dst, ew, E);

    // P = feat @ W
    gemm_kernel<<<(N_NODES + 15) / 16, 256>>>(feat, W);

    // out = 0.5*(P + sum w*P[src])
    gather_kernel<<<(N_NODES * 32 + 255) / 256, 256>>>(out);
}